// round 13
// baseline (speedup 1.0000x reference)
#include <cuda_runtime.h>
#include <cstdint>

#define BSZ 2
#define NN  4096
#define JJ  3
#define CC  32
#define KO  32
#define MJ  (NN*JJ)               // 12288
#define BM  256
#define BKT 32
#define NTILES (NN/BM)            // 16
#define CHUNKS (MJ/BKT)           // 384
#define TOTAL_STEPS (BSZ*NTILES*CHUNKS)   // 12288
#define NBLK 148                  // one persistent block per SM
#define WS  36                    // padded stride (conflict-free frags)
#define STAGES 6
#define STAGE_WORDS (BM * WS)                 // 9216 (W only)
#define GEMM_SMEM (STAGES * STAGE_WORDS * 4)  // 221184 B

__device__ float g_t[BSZ * MJ * KO];          // t[b][mj][k] (tf32 bits)

__device__ __forceinline__ uint32_t f2tf32(float f) {
    uint32_t o;
    asm("cvt.rna.tf32.f32 %0, %1;" : "=r"(o) : "f"(f));
    return o;
}

// ---------------------------------------------------------------------------
// Fused: out[b][k][n] = bias[k]  AND  t[bm][j*32+k] = (1+2^-11)*sum_c cw*x
// ---------------------------------------------------------------------------
__global__ __launch_bounds__(256) void precompute_t_kernel(const float* __restrict__ x,
                                                           const float* __restrict__ cw,
                                                           float* __restrict__ out,
                                                           const float* __restrict__ cb) {
    __shared__ float cws[KO * 100];
    __shared__ float xs[16 * WS];

    const int tid = threadIdx.x;
    const int bm0 = blockIdx.x * 16;

    {   // out init: 512 elements per block, 2 per thread (same k)
        int idx = blockIdx.x * 512 + tid * 2;
        float bk = cb[(idx >> 12) & 31];
        *(float2*)(out + idx) = make_float2(bk, bk);
    }

#pragma unroll
    for (int p = 0; p < 3; ++p) {
        int idx = p * 256 + tid;               // 768 float4 of conv_w
        int r = idx / 24, cv = idx % 24;
        float4 v = ((const float4*)cw)[idx];
        *(float4*)(cws + r * 100 + cv * 4) = v;
    }
    if (tid < 128) {
        int r = tid >> 3, cv = tid & 7;
        float4 v = ((const float4*)(x + (size_t)bm0 * CC))[tid];
        *(float4*)(xs + r * WS + cv * 4) = v;
    }
    __syncthreads();

#pragma unroll
    for (int p = 0; p < 6; ++p) {
        int o = p * 256 + tid;                 // 0..1535
        int bm = o / 96, jk = o % 96;
        int j = jk >> 5, k = jk & 31;
        const float* xr = xs + bm * WS;
        const float* wr = cws + k * 100 + j * 32;
        float s = 0.f;
#pragma unroll
        for (int cv = 0; cv < 8; ++cv) {
            float4 xv = *(const float4*)(xr + cv * 4);
            float4 wv = *(const float4*)(wr + cv * 4);
            s = fmaf(xv.x, wv.x, s);
            s = fmaf(xv.y, wv.y, s);
            s = fmaf(xv.z, wv.z, s);
            s = fmaf(xv.w, wv.w, s);
        }
        s *= (1.0f + 4.8828125e-4f);           // cancel tf32 truncation bias on W
        ((uint32_t*)g_t)[(size_t)bm0 * 96 + o] = f2tf32(s);
    }
}

// ---------------------------------------------------------------------------
// Decoupled-warp persistent split-K tf32 GEMM. Each warp owns 32 rows of the
// BM=256 tile: fills its own smem quarter via its own cp.async chain (6-stage
// ring, 5 in flight), reads B frags straight from g_t via __ldg with a
// one-tile register prefetch. NO barriers in the mainloop.
// ---------------------------------------------------------------------------
extern __shared__ uint32_t smem_dyn[];

__device__ __forceinline__ void mma8(float* a4, uint32_t a0, uint32_t a1,
                                     uint32_t a2, uint32_t a3,
                                     uint32_t b0, uint32_t b1) {
    asm volatile(
        "mma.sync.aligned.m16n8k8.row.col.f32.tf32.tf32.f32 "
        "{%0,%1,%2,%3}, {%4,%5,%6,%7}, {%8,%9}, {%0,%1,%2,%3};"
        : "+f"(a4[0]), "+f"(a4[1]), "+f"(a4[2]), "+f"(a4[3])
        : "r"(a0), "r"(a1), "r"(a2), "r"(a3), "r"(b0), "r"(b1));
}

__global__ __launch_bounds__(256, 1) void gemm_kernel(const float* __restrict__ W,
                                                      float* __restrict__ out) {
    const int tid  = threadIdx.x;
    const int warp = tid >> 5, lane = tid & 31;
    const int lg   = lane >> 2, lt = lane & 3;
    const int row0 = warp * 32;

    int s0 = (int)(((long long)blockIdx.x * TOTAL_STEPS) / NBLK);
    const int s_end = (int)(((long long)(blockIdx.x + 1) * TOTAL_STEPS) / NBLK);

    while (s0 < s_end) {
        const int tile = s0 / CHUNKS;
        const int seg_end = min(s_end, (tile + 1) * CHUNKS);
        const int len = seg_end - s0;
        const int b  = tile >> 4;
        const int n0 = (tile & 15) * BM;
        const int kk0 = (s0 - tile * CHUNKS) * BKT;

        const float* Wbase = W + ((size_t)(b * NN + n0)) * MJ + kk0;
        const uint32_t* tb = (const uint32_t*)g_t + ((size_t)b * MJ + kk0) * KO;

        float acc[2][4][4];
#pragma unroll
        for (int m = 0; m < 2; ++m)
#pragma unroll
            for (int i = 0; i < 4; ++i)
#pragma unroll
                for (int j = 0; j < 4; ++j) acc[m][i][j] = 0.f;

// warp fills ONLY its own 32 rows: 8 chunks of 16B per lane, coalesced.
#define FILL(sidx, t)                                                             \
    {                                                                             \
        uint32_t* Wst = smem_dyn + (sidx) * STAGE_WORDS;                          \
        const float* wp_ = Wbase + (t) * BKT;                                     \
        _Pragma("unroll")                                                         \
        for (int q = 0; q < 8; ++q) {                                             \
            int idx_ = q * 32 + lane;                                             \
            int r_ = row0 + (idx_ >> 3);                                          \
            int c_ = (idx_ & 7) * 4;                                              \
            uint32_t d_ = (uint32_t)__cvta_generic_to_shared(&Wst[r_ * WS + c_]); \
            asm volatile("cp.async.cg.shared.global [%0], [%1], 16;" ::           \
                         "r"(d_), "l"(wp_ + (size_t)r_ * MJ + c_));               \
        }                                                                         \
    }

#define LOADB(dst, t)                                                             \
    {                                                                             \
        const uint32_t* p_ = tb + (size_t)(t) * (BKT * KO);                       \
        _Pragma("unroll")                                                         \
        for (int s4_ = 0; s4_ < 4; ++s4_)                                         \
            _Pragma("unroll")                                                     \
            for (int nt_ = 0; nt_ < 4; ++nt_) {                                   \
                dst[s4_ * 8 + nt_ * 2]     = __ldg(p_ + (s4_*8 + lt)   * KO + nt_*8 + lg); \
                dst[s4_ * 8 + nt_ * 2 + 1] = __ldg(p_ + (s4_*8 + lt+4) * KO + nt_*8 + lg); \
            }                                                                     \
    }

#define COMPUTE(sidx, br)                                                         \
    {                                                                             \
        const uint32_t* Ws = smem_dyn + (sidx) * STAGE_WORDS;                     \
        _Pragma("unroll")                                                         \
        for (int s4_ = 0; s4_ < 4; ++s4_) {                                       \
            const int kc_ = s4_ * 8;                                              \
            uint32_t a00 = Ws[(row0 + lg)      * WS + kc_ + lt];                  \
            uint32_t a01 = Ws[(row0 + lg + 8)  * WS + kc_ + lt];                  \
            uint32_t a02 = Ws[(row0 + lg)      * WS + kc_ + lt + 4];              \
            uint32_t a03 = Ws[(row0 + lg + 8)  * WS + kc_ + lt + 4];              \
            uint32_t a10 = Ws[(row0 + lg + 16) * WS + kc_ + lt];                  \
            uint32_t a11 = Ws[(row0 + lg + 24) * WS + kc_ + lt];                  \
            uint32_t a12 = Ws[(row0 + lg + 16) * WS + kc_ + lt + 4];              \
            uint32_t a13 = Ws[(row0 + lg + 24) * WS + kc_ + lt + 4];              \
            _Pragma("unroll")                                                     \
            for (int nt_ = 0; nt_ < 4; ++nt_) {                                   \
                uint32_t b0_ = br[s4_ * 8 + nt_ * 2];                             \
                uint32_t b1_ = br[s4_ * 8 + nt_ * 2 + 1];                         \
                mma8(acc[0][nt_], a00, a01, a02, a03, b0_, b1_);                  \
                mma8(acc[1][nt_], a10, a11, a12, a13, b0_, b1_);                  \
            }                                                                     \
        }                                                                         \
    }

        // prefill 5 tiles (commit every slot so group counting is uniform)
#pragma unroll
        for (int pf = 0; pf < 5; ++pf) {
            if (pf < len) FILL(pf, pf);
            asm volatile("cp.async.commit_group;");
        }

        uint32_t bA[32], bB[32];
        LOADB(bA, 0);

        int sc = 0, sf = 5;
        int it = 0;
        for (; it + 1 < len; it += 2) {
            asm volatile("cp.async.wait_group 4;");       // own tile it landed
            if (it + 5 < len) FILL(sf, it + 5);
            asm volatile("cp.async.commit_group;");
            sf = (sf == 5) ? 0 : sf + 1;
            LOADB(bB, it + 1);
            COMPUTE(sc, bA);
            sc = (sc == 5) ? 0 : sc + 1;

            asm volatile("cp.async.wait_group 4;");       // own tile it+1 landed
            if (it + 6 < len) FILL(sf, it + 6);
            asm volatile("cp.async.commit_group;");
            sf = (sf == 5) ? 0 : sf + 1;
            if (it + 2 < len) LOADB(bA, it + 2);
            COMPUTE(sc, bB);
            sc = (sc == 5) ? 0 : sc + 1;
        }
        if (it < len) {
            asm volatile("cp.async.wait_group 4;");
            COMPUTE(sc, bA);
        }
#undef FILL
#undef LOADB
#undef COMPUTE

        // ---- flush segment: stage 256x32 in smem (stride 33), coalesced REDG ----
        asm volatile("cp.async.wait_group 0;");           // own chain drained
        __syncthreads();                                  // everyone drained
        float* stg = (float*)smem_dyn;                    // 33.8 KB staging
#pragma unroll
        for (int m = 0; m < 2; ++m)
#pragma unroll
            for (int nt = 0; nt < 4; ++nt) {
                int col = nt * 8 + lt * 2;
                int r = row0 + m * 16 + lg;
                stg[r * 33 + col]           = acc[m][nt][0];
                stg[r * 33 + col + 1]       = acc[m][nt][1];
                stg[(r + 8) * 33 + col]     = acc[m][nt][2];
                stg[(r + 8) * 33 + col + 1] = acc[m][nt][3];
            }
        __syncthreads();
        float* obase = out + (size_t)b * (KO * NN);
#pragma unroll
        for (int p = 0; p < 32; ++p) {
            int idx = p * 256 + tid;           // 8192 outputs
            int nl = idx & 255, k = idx >> 8;
            atomicAdd(obase + (size_t)k * NN + n0 + nl, stg[nl * 33 + k]);
        }
        __syncthreads();                        // staging freed before next FILL

        s0 = seg_end;
    }
}

// ---------------------------------------------------------------------------
extern "C" void kernel_launch(void* const* d_in, const int* in_sizes, int n_in,
                              void* d_out, int out_size) {
    const float* W  = (const float*)d_in[0];
    const float* x  = (const float*)d_in[1];
    const float* cw = (const float*)d_in[2];
    const float* cb = (const float*)d_in[3];
    float* out = (float*)d_out;

    static int attr_set = 0;
    if (!attr_set) {
        cudaFuncSetAttribute(gemm_kernel,
                             cudaFuncAttributeMaxDynamicSharedMemorySize, GEMM_SMEM);
        attr_set = 1;
    }

    precompute_t_kernel<<<(BSZ * NN) / 16, 256>>>(x, cw, out, cb);
    gemm_kernel<<<NBLK, 256, GEMM_SMEM>>>(W, out);
}

// round 14
// speedup vs baseline: 1.1385x; 1.1385x over previous
#include <cuda_runtime.h>
#include <cstdint>

#define BSZ 2
#define NN  4096
#define JJ  3
#define CC  32
#define KO  32
#define MJ  (NN*JJ)               // 12288
#define BM  256
#define BKT 32
#define NTILES (NN/BM)            // 16
#define CHUNKS (MJ/BKT)           // 384
#define TOTAL_STEPS (BSZ*NTILES*CHUNKS)   // 12288
#define NBLK 148                  // one persistent block per SM
#define WS  36                    // W stride: a-frag banks 4*lg+lt, conflict-free
#define WST 40                    // t stride: b-frag banks 8*lt+lg, conflict-free
#define STAGES 5
#define STAGE_WORDS (BM*WS + BKT*WST)         // 10496
#define GEMM_SMEM (STAGES * STAGE_WORDS * 4)  // 209920 B

__device__ float g_t[BSZ * MJ * KO];          // t[b][mj][k] (tf32 bits)

__device__ __forceinline__ uint32_t f2tf32(float f) {
    uint32_t o;
    asm("cvt.rna.tf32.f32 %0, %1;" : "=r"(o) : "f"(f));
    return o;
}

// ---------------------------------------------------------------------------
// Fused: out[b][k][n] = bias[k]  AND  t[bm][j*32+k] = (1+2^-11)*sum_c cw*x
// ---------------------------------------------------------------------------
__global__ __launch_bounds__(256) void precompute_t_kernel(const float* __restrict__ x,
                                                           const float* __restrict__ cw,
                                                           float* __restrict__ out,
                                                           const float* __restrict__ cb) {
    __shared__ float cws[KO * 100];
    __shared__ float xs[16 * WS];

    const int tid = threadIdx.x;
    const int bm0 = blockIdx.x * 16;

    {   // out init: 512 elements per block, 2 per thread (same k)
        int idx = blockIdx.x * 512 + tid * 2;
        float bk = cb[(idx >> 12) & 31];
        *(float2*)(out + idx) = make_float2(bk, bk);
    }

#pragma unroll
    for (int p = 0; p < 3; ++p) {
        int idx = p * 256 + tid;               // 768 float4 of conv_w
        int r = idx / 24, cv = idx % 24;
        float4 v = ((const float4*)cw)[idx];
        *(float4*)(cws + r * 100 + cv * 4) = v;
    }
    if (tid < 128) {
        int r = tid >> 3, cv = tid & 7;
        float4 v = ((const float4*)(x + (size_t)bm0 * CC))[tid];
        *(float4*)(xs + r * WS + cv * 4) = v;
    }
    __syncthreads();

#pragma unroll
    for (int p = 0; p < 6; ++p) {
        int o = p * 256 + tid;                 // 0..1535
        int bm = o / 96, jk = o % 96;
        int j = jk >> 5, k = jk & 31;
        const float* xr = xs + bm * WS;
        const float* wr = cws + k * 100 + j * 32;
        float s = 0.f;
#pragma unroll
        for (int cv = 0; cv < 8; ++cv) {
            float4 xv = *(const float4*)(xr + cv * 4);
            float4 wv = *(const float4*)(wr + cv * 4);
            s = fmaf(xv.x, wv.x, s);
            s = fmaf(xv.y, wv.y, s);
            s = fmaf(xv.z, wv.z, s);
            s = fmaf(xv.w, wv.w, s);
        }
        s *= (1.0f + 4.8828125e-4f);           // cancel tf32 truncation bias on W
        ((uint32_t*)g_t)[(size_t)bm0 * 96 + o] = f2tf32(s);
    }
}

// ---------------------------------------------------------------------------
// Balanced persistent split-K tf32 GEMM, 5-stage cp.async ring (4 tiles in
// flight). BM=256: 8 warps x 32 rows (2 m16 subtiles/warp). B tile stride 40
// -> conflict-free b-frag LDS.
// ---------------------------------------------------------------------------
extern __shared__ uint32_t smem_dyn[];

__global__ __launch_bounds__(256, 1) void gemm_kernel(const float* __restrict__ W,
                                                      float* __restrict__ out) {
    const int tid  = threadIdx.x;
    const int warp = tid >> 5, lane = tid & 31;
    const int lg   = lane >> 2, lt = lane & 3;
    const int row0 = warp * 32;

    const int wlr = tid >> 3;              // W tile: 8 rows/thread (+q*32)
    const int wlc = (tid & 7) * 4;
    const int tkk = tid >> 3;              // t tile: 1 float4/thread
    const int tko = (tid & 7) * 4;

    int s0 = (int)(((long long)blockIdx.x * TOTAL_STEPS) / NBLK);
    const int s_end = (int)(((long long)(blockIdx.x + 1) * TOTAL_STEPS) / NBLK);

    while (s0 < s_end) {
        const int tile = s0 / CHUNKS;
        const int seg_end = min(s_end, (tile + 1) * CHUNKS);
        const int len = seg_end - s0;
        const int b  = tile >> 4;
        const int n0 = (tile & 15) * BM;
        const int kk0 = (s0 - tile * CHUNKS) * BKT;

        const float* Wbase = W   + ((size_t)(b * NN + n0)) * MJ + kk0;
        const float* Tbase = g_t + ((size_t)b * MJ + kk0) * KO;

        float acc[2][4][4];
#pragma unroll
        for (int m = 0; m < 2; ++m)
#pragma unroll
            for (int i = 0; i < 4; ++i)
#pragma unroll
                for (int j = 0; j < 4; ++j) acc[m][i][j] = 0.f;

#define FILL(s, t)                                                                \
    {                                                                             \
        uint32_t* Wst = smem_dyn + (s) * STAGE_WORDS;                             \
        uint32_t* Tst = Wst + BM * WS;                                            \
        const float* wp_ = Wbase + (t) * BKT;                                     \
        _Pragma("unroll")                                                         \
        for (int q = 0; q < 8; ++q) {                                             \
            uint32_t d_ = (uint32_t)__cvta_generic_to_shared(                     \
                &Wst[(wlr + q * 32) * WS + wlc]);                                 \
            asm volatile("cp.async.cg.shared.global [%0], [%1], 16;" ::           \
                         "r"(d_), "l"(wp_ + (size_t)(wlr + q * 32) * MJ + wlc));  \
        }                                                                         \
        uint32_t dt_ = (uint32_t)__cvta_generic_to_shared(                        \
            &Tst[tkk * WST + tko]);                                               \
        asm volatile("cp.async.cg.shared.global [%0], [%1], 16;" ::               \
                     "r"(dt_), "l"(Tbase + (t) * (BKT * KO) + tid * 4));          \
    }

        // prefill up to 4 tiles, one commit group each
#pragma unroll
        for (int pf = 0; pf < 4; ++pf) {
            if (pf < len) FILL(pf, pf);
            asm volatile("cp.async.commit_group;");
        }

        for (int it = 0; it < len; ++it) {
            asm volatile("cp.async.wait_group 3;");   // oldest tile landed
            __syncthreads();                          // visible; compute(it-1) done
            if (it + 4 < len) FILL((it + 4) % STAGES, it + 4);
            asm volatile("cp.async.commit_group;");

            const uint32_t* Ws = smem_dyn + (it % STAGES) * STAGE_WORDS;
            const uint32_t* Ts = Ws + BM * WS;
#pragma unroll
            for (int s4 = 0; s4 < 4; ++s4) {
                const int kc = s4 * 8;
                uint32_t a[2][4];
#pragma unroll
                for (int m = 0; m < 2; ++m) {
                    int r = row0 + m * 16 + lg;
                    a[m][0] = Ws[r * WS + kc + lt];
                    a[m][1] = Ws[(r + 8) * WS + kc + lt];
                    a[m][2] = Ws[r * WS + kc + lt + 4];
                    a[m][3] = Ws[(r + 8) * WS + kc + lt + 4];
                }
#pragma unroll
                for (int nt = 0; nt < 4; ++nt) {
                    uint32_t b0 = Ts[(kc + lt)     * WST + nt * 8 + lg];
                    uint32_t b1 = Ts[(kc + lt + 4) * WST + nt * 8 + lg];
#pragma unroll
                    for (int m = 0; m < 2; ++m) {
                        asm volatile(
                            "mma.sync.aligned.m16n8k8.row.col.f32.tf32.tf32.f32 "
                            "{%0,%1,%2,%3}, {%4,%5,%6,%7}, {%8,%9}, {%0,%1,%2,%3};"
                            : "+f"(acc[m][nt][0]), "+f"(acc[m][nt][1]),
                              "+f"(acc[m][nt][2]), "+f"(acc[m][nt][3])
                            : "r"(a[m][0]), "r"(a[m][1]), "r"(a[m][2]), "r"(a[m][3]),
                              "r"(b0), "r"(b1));
                    }
                }
            }
        }
#undef FILL

        // ---- flush segment: stage 256x32 in smem (stride 33), coalesced REDG ----
        asm volatile("cp.async.wait_group 0;");
        __syncthreads();
        float* stg = (float*)smem_dyn;                // 33.8 KB
#pragma unroll
        for (int m = 0; m < 2; ++m)
#pragma unroll
            for (int nt = 0; nt < 4; ++nt) {
                int col = nt * 8 + lt * 2;
                int r = row0 + m * 16 + lg;
                stg[r * 33 + col]           = acc[m][nt][0];
                stg[r * 33 + col + 1]       = acc[m][nt][1];
                stg[(r + 8) * 33 + col]     = acc[m][nt][2];
                stg[(r + 8) * 33 + col + 1] = acc[m][nt][3];
            }
        __syncthreads();
        float* obase = out + (size_t)b * (KO * NN);
#pragma unroll
        for (int p = 0; p < 32; ++p) {
            int idx = p * 256 + tid;           // 8192 outputs
            int nl = idx & 255, k = idx >> 8;
            atomicAdd(obase + (size_t)k * NN + n0 + nl, stg[nl * 33 + k]);
        }
        __syncthreads();                        // staging freed before next FILL

        s0 = seg_end;
    }
}

// ---------------------------------------------------------------------------
extern "C" void kernel_launch(void* const* d_in, const int* in_sizes, int n_in,
                              void* d_out, int out_size) {
    const float* W  = (const float*)d_in[0];
    const float* x  = (const float*)d_in[1];
    const float* cw = (const float*)d_in[2];
    const float* cb = (const float*)d_in[3];
    float* out = (float*)d_out;

    static int attr_set = 0;
    if (!attr_set) {
        cudaFuncSetAttribute(gemm_kernel,
                             cudaFuncAttributeMaxDynamicSharedMemorySize, GEMM_SMEM);
        attr_set = 1;
    }

    precompute_t_kernel<<<(BSZ * NN) / 16, 256>>>(x, cw, out, cb);
    gemm_kernel<<<NBLK, 256, GEMM_SMEM>>>(W, out);
}

// round 15
// speedup vs baseline: 1.3466x; 1.1828x over previous
#include <cuda_runtime.h>
#include <cstdint>

#define BSZ 2
#define NN  4096
#define JJ  3
#define CC  32
#define KO  32
#define MJ  (NN*JJ)               // 12288
#define BM  256
#define BKT 64
#define NTILES (NN/BM)            // 16
#define CHUNKS (MJ/BKT)           // 192
#define TOTAL_STEPS (BSZ*NTILES*CHUNKS)   // 6144
#define NBLK 148                  // one persistent block per SM
#define WST 40                    // t stride: b-frag banks 8*lt+lg, conflict-free
#define STAGES 3
#define W_WORDS (BM*BKT)                      // 16384 (swizzled, no padding)
#define STAGE_WORDS (W_WORDS + BKT*WST)       // 18944
#define GEMM_SMEM (STAGES * STAGE_WORDS * 4)  // 227328 B

__device__ float g_t[BSZ * MJ * KO];          // t[b][mj][k] (tf32 bits)

__device__ __forceinline__ uint32_t f2tf32(float f) {
    uint32_t o;
    asm("cvt.rna.tf32.f32 %0, %1;" : "=r"(o) : "f"(f));
    return o;
}

// ---------------------------------------------------------------------------
// Fused: out[b][k][n] = bias[k]  AND  t[bm][j*32+k] = (1+2^-11)*sum_c cw*x
// ---------------------------------------------------------------------------
__global__ __launch_bounds__(256) void precompute_t_kernel(const float* __restrict__ x,
                                                           const float* __restrict__ cw,
                                                           float* __restrict__ out,
                                                           const float* __restrict__ cb) {
    __shared__ float cws[KO * 100];
    __shared__ float xs[16 * 36];

    const int tid = threadIdx.x;
    const int bm0 = blockIdx.x * 16;

    {   // out init: 512 elements per block, 2 per thread (same k)
        int idx = blockIdx.x * 512 + tid * 2;
        float bk = cb[(idx >> 12) & 31];
        *(float2*)(out + idx) = make_float2(bk, bk);
    }

#pragma unroll
    for (int p = 0; p < 3; ++p) {
        int idx = p * 256 + tid;               // 768 float4 of conv_w
        int r = idx / 24, cv = idx % 24;
        float4 v = ((const float4*)cw)[idx];
        *(float4*)(cws + r * 100 + cv * 4) = v;
    }
    if (tid < 128) {
        int r = tid >> 3, cv = tid & 7;
        float4 v = ((const float4*)(x + (size_t)bm0 * CC))[tid];
        *(float4*)(xs + r * 36 + cv * 4) = v;
    }
    __syncthreads();

#pragma unroll
    for (int p = 0; p < 6; ++p) {
        int o = p * 256 + tid;                 // 0..1535
        int bm = o / 96, jk = o % 96;
        int j = jk >> 5, k = jk & 31;
        const float* xr = xs + bm * 36;
        const float* wr = cws + k * 100 + j * 32;
        float s = 0.f;
#pragma unroll
        for (int cv = 0; cv < 8; ++cv) {
            float4 xv = *(const float4*)(xr + cv * 4);
            float4 wv = *(const float4*)(wr + cv * 4);
            s = fmaf(xv.x, wv.x, s);
            s = fmaf(xv.y, wv.y, s);
            s = fmaf(xv.z, wv.z, s);
            s = fmaf(xv.w, wv.w, s);
        }
        s *= (1.0f + 4.8828125e-4f);           // cancel tf32 truncation bias on W
        ((uint32_t*)g_t)[(size_t)bm0 * 96 + o] = f2tf32(s);
    }
}

// ---------------------------------------------------------------------------
// Balanced persistent split-K tf32 GEMM. BKT=64 (256 B/row bursts), XOR-
// swizzled W tile (no padding), 3-stage ring (2 tiles in flight).
// 8 warps x 32 rows (2 m16 subtiles/warp).
// ---------------------------------------------------------------------------
extern __shared__ uint32_t smem_dyn[];

__global__ __launch_bounds__(256, 1) void gemm_kernel(const float* __restrict__ W,
                                                      float* __restrict__ out) {
    const int tid  = threadIdx.x;
    const int warp = tid >> 5, lane = tid & 31;
    const int lg   = lane >> 2, lt = lane & 3;
    const int row0 = warp * 32;
    const int swz  = lg << 2;              // a-frag swizzle term (row&7 == lg)

    int s0 = (int)(((long long)blockIdx.x * TOTAL_STEPS) / NBLK);
    const int s_end = (int)(((long long)(blockIdx.x + 1) * TOTAL_STEPS) / NBLK);

    while (s0 < s_end) {
        const int tile = s0 / CHUNKS;
        const int seg_end = min(s_end, (tile + 1) * CHUNKS);
        const int len = seg_end - s0;
        const int b  = tile >> 4;
        const int n0 = (tile & 15) * BM;
        const int kk0 = (s0 - tile * CHUNKS) * BKT;

        const float* Wbase = W   + ((size_t)(b * NN + n0)) * MJ + kk0;
        const float* Tbase = g_t + ((size_t)b * MJ + kk0) * KO;

        float acc[2][4][4];
#pragma unroll
        for (int m = 0; m < 2; ++m)
#pragma unroll
            for (int i = 0; i < 4; ++i)
#pragma unroll
                for (int j = 0; j < 4; ++j) acc[m][i][j] = 0.f;

#define FILL(s, t)                                                                \
    {                                                                             \
        uint32_t* Wst = smem_dyn + (s) * STAGE_WORDS;                             \
        uint32_t* Tst = Wst + W_WORDS;                                            \
        const float* wp_ = Wbase + (t) * BKT;                                     \
        _Pragma("unroll")                                                         \
        for (int q = 0; q < 16; ++q) {                                            \
            int idx_ = q * 256 + tid;                                             \
            int r_ = idx_ >> 4;                                                   \
            int c_ = (idx_ & 15) * 4;                                             \
            uint32_t d_ = (uint32_t)__cvta_generic_to_shared(                     \
                &Wst[r_ * BKT + (c_ ^ ((r_ & 7) << 2))]);                         \
            asm volatile("cp.async.cg.shared.global [%0], [%1], 16;" ::           \
                         "r"(d_), "l"(wp_ + (size_t)r_ * MJ + c_));               \
        }                                                                         \
        _Pragma("unroll")                                                         \
        for (int q = 0; q < 2; ++q) {                                             \
            int idx_ = q * 256 + tid;                                             \
            int kk_ = idx_ >> 3;                                                  \
            int ko_ = (idx_ & 7) * 4;                                             \
            uint32_t d_ = (uint32_t)__cvta_generic_to_shared(                     \
                &Tst[kk_ * WST + ko_]);                                           \
            asm volatile("cp.async.cg.shared.global [%0], [%1], 16;" ::           \
                         "r"(d_), "l"(Tbase + ((size_t)(t) * BKT + kk_) * KO + ko_)); \
        }                                                                         \
    }

        // prefill 2 tiles
        if (0 < len) FILL(0, 0);
        asm volatile("cp.async.commit_group;");
        if (1 < len) FILL(1, 1);
        asm volatile("cp.async.commit_group;");

        for (int it = 0; it < len; ++it) {
            asm volatile("cp.async.wait_group 1;");   // tile it arrived
            __syncthreads();                          // visible; compute(it-1) done
            if (it + 2 < len) FILL((it + 2) % 3, it + 2);
            asm volatile("cp.async.commit_group;");

            const uint32_t* Ws = smem_dyn + (it % 3) * STAGE_WORDS;
            const uint32_t* Ts = Ws + W_WORDS;
#pragma unroll
            for (int s4 = 0; s4 < 8; ++s4) {
                const int kc = s4 * 8;
                const int c0 = (kc + lt) ^ swz;
                const int c1 = (kc + lt + 4) ^ swz;
                uint32_t a[2][4];
#pragma unroll
                for (int m = 0; m < 2; ++m) {
                    int r = row0 + m * 16 + lg;
                    a[m][0] = Ws[r * BKT + c0];
                    a[m][1] = Ws[(r + 8) * BKT + c0];
                    a[m][2] = Ws[r * BKT + c1];
                    a[m][3] = Ws[(r + 8) * BKT + c1];
                }
#pragma unroll
                for (int nt = 0; nt < 4; ++nt) {
                    uint32_t b0 = Ts[(kc + lt)     * WST + nt * 8 + lg];
                    uint32_t b1 = Ts[(kc + lt + 4) * WST + nt * 8 + lg];
#pragma unroll
                    for (int m = 0; m < 2; ++m) {
                        asm volatile(
                            "mma.sync.aligned.m16n8k8.row.col.f32.tf32.tf32.f32 "
                            "{%0,%1,%2,%3}, {%4,%5,%6,%7}, {%8,%9}, {%0,%1,%2,%3};"
                            : "+f"(acc[m][nt][0]), "+f"(acc[m][nt][1]),
                              "+f"(acc[m][nt][2]), "+f"(acc[m][nt][3])
                            : "r"(a[m][0]), "r"(a[m][1]), "r"(a[m][2]), "r"(a[m][3]),
                              "r"(b0), "r"(b1));
                    }
                }
            }
        }
#undef FILL

        // ---- flush segment: stage 256x32 in smem (stride 33), coalesced REDG ----
        asm volatile("cp.async.wait_group 0;");
        __syncthreads();
        float* stg = (float*)smem_dyn;                // 33.8 KB
#pragma unroll
        for (int m = 0; m < 2; ++m)
#pragma unroll
            for (int nt = 0; nt < 4; ++nt) {
                int col = nt * 8 + lt * 2;
                int r = row0 + m * 16 + lg;
                stg[r * 33 + col]           = acc[m][nt][0];
                stg[r * 33 + col + 1]       = acc[m][nt][1];
                stg[(r + 8) * 33 + col]     = acc[m][nt][2];
                stg[(r + 8) * 33 + col + 1] = acc[m][nt][3];
            }
        __syncthreads();
        float* obase = out + (size_t)b * (KO * NN);
#pragma unroll
        for (int p = 0; p < 32; ++p) {
            int idx = p * 256 + tid;           // 8192 outputs
            int nl = idx & 255, k = idx >> 8;
            atomicAdd(obase + (size_t)k * NN + n0 + nl, stg[nl * 33 + k]);
        }
        __syncthreads();                        // staging freed before next FILL

        s0 = seg_end;
    }
}

// ---------------------------------------------------------------------------
extern "C" void kernel_launch(void* const* d_in, const int* in_sizes, int n_in,
                              void* d_out, int out_size) {
    const float* W  = (const float*)d_in[0];
    const float* x  = (const float*)d_in[1];
    const float* cw = (const float*)d_in[2];
    const float* cb = (const float*)d_in[3];
    float* out = (float*)d_out;

    static int attr_set = 0;
    if (!attr_set) {
        cudaFuncSetAttribute(gemm_kernel,
                             cudaFuncAttributeMaxDynamicSharedMemorySize, GEMM_SMEM);
        attr_set = 1;
    }

    precompute_t_kernel<<<(BSZ * NN) / 16, 256>>>(x, cw, out, cb);
    gemm_kernel<<<NBLK, 256, GEMM_SMEM>>>(W, out);
}